// round 16
// baseline (speedup 1.0000x reference)
#include <cuda_runtime.h>
#include <cuda_fp16.h>
#include <cstdint>

#define BB 1024
#define TT 256
#define EE 384
#define HH 64

// Only W needs global scratch now (no-allocation rule: __device__ global).
__device__ __half g_wh[3 * HH * EE];   // [m*64+n][k], pair-permuted within 16-k groups

// ---------------------------------------------------------------------------
// helpers
// ---------------------------------------------------------------------------
__device__ __forceinline__ float ex2f(float x) {
    float y;
    asm("ex2.approx.ftz.f32 %0, %1;" : "=f"(y) : "f"(x));
    return y;
}
__device__ __forceinline__ uint32_t pk2h(float lo, float hi) {
    __half2 h = __floats2half2_rn(lo, hi);       // .x = lo half
    return *reinterpret_cast<uint32_t*>(&h);
}
// m16n8k16 fp16 mma, fp32 accumulate (baseline PTX, compute_103-legal).
__device__ __forceinline__ void mma16h(float* d, const uint32_t* a, uint32_t b0, uint32_t b1) {
    asm("mma.sync.aligned.m16n8k16.row.col.f32.f16.f16.f32 "
        "{%0,%1,%2,%3}, {%4,%5,%6,%7}, {%8,%9}, {%0,%1,%2,%3};"
        : "+f"(d[0]), "+f"(d[1]), "+f"(d[2]), "+f"(d[3])
        : "r"(a[0]), "r"(a[1]), "r"(a[2]), "r"(a[3]), "r"(b0), "r"(b1));
}
__device__ __forceinline__ void cpa16(uint32_t dst, const void* src) {
    asm volatile("cp.async.cg.shared.global [%0], [%1], 16;" :: "r"(dst), "l"(src));
}
__device__ __forceinline__ uint32_t smem_u32(const void* p) {
    uint32_t a;
    asm("{ .reg .u64 t; cvta.to.shared.u64 t, %1; cvt.u32.u64 %0, t; }" : "=r"(a) : "l"(p));
    return a;
}
__device__ __forceinline__ float shflx(float v, int m) {
    return __shfl_xor_sync(0xffffffffu, v, m);
}

// ---------------------------------------------------------------------------
// Kernel 0: W -> fp16, pair-permuted within 16-k groups (reader maps phys
// pair pp -> logical (pp>>1)+((pp&1)<<2)).
// ---------------------------------------------------------------------------
__global__ void wt_kernel(const float* __restrict__ Wq, const float* __restrict__ Wk,
                          const float* __restrict__ Wv) {
    int idx = blockIdx.x * 256 + threadIdx.x;
    if (idx >= 3 * HH * EE) return;
    int m  = idx / (HH * EE);
    int n  = (idx / EE) & 63;
    int kp = idx % EE;
    int p  = kp & 15;
    int pp = p >> 1;
    int lp = (pp >> 1) + ((pp & 1) << 2);
    int k  = (kp & ~15) + 2 * lp + (p & 1);
    const float* W = (m == 0) ? Wq : (m == 1) ? Wk : Wv;
    g_wh[idx] = __float2half_rn(W[k * HH + n]);
}

// ---------------------------------------------------------------------------
// Fused kernel: one CTA per batch (512 thr / 16 warps).
// Phase 1 (qkv): 256 rows x 192 cols, warps 8(M)x2(N), 12 k-chunks of 32
//   (2 k16 steps), double-buffered cp.async. Same mma layouts as R15.
// Transition: epilogue STS's accumulators directly into the attn smem
//   layouts (q/k rows head-pair-permuted; V transposed + token-permuted),
//   overlaying the dead stage buffers. No global q/k/v round trip.
// Phase 2 (attn): R15 mainloop — warp w owns tile w, nch=(w+4)>>2, no
//   online max (exact), P = f16x2 register packing.
// smem: stages 2 x 59,392 B; attn overlay qs(0)/ks(36864)/vst(73728). 116 KB.
// ---------------------------------------------------------------------------
#define XS_BYTES 40960                     // 256 rows * 160 B (40 f32, swizzled)
#define QS_STAGE (XS_BYTES + 18432)        // + ws: 192 rows * 96 B
#define A_QS 0
#define A_KS 36864
#define A_VS 73728
#define FUSED_SMEM (2 * QS_STAGE)          // 118,784 B (>= A_VS + 64*552)

__device__ __forceinline__ void qkv_load(uint32_t sbase, int stage, int chunk,
                                         const float* __restrict__ x, long long r0) {
    uint32_t xs = sbase + stage * QS_STAGE;
    uint32_t ws = xs + XS_BYTES;
    int tid = threadIdx.x;
#pragma unroll
    for (int i = 0; i < 4; i++) {                 // x: 256 rows x 32 f32 = 2048 lines
        int idx = tid + i * 512;
        int row = idx >> 3, c16 = idx & 7;
        uint32_t doff = (uint32_t)(c16 * 16) ^ (uint32_t)((row & 4) << 2);
        cpa16(xs + row * 160 + doff, x + (r0 + row) * EE + chunk * 32 + c16 * 4);
    }
#pragma unroll
    for (int i = 0; i < 2; i++) {                 // W: 192 rows x 64 B = 768 lines
        int idx = tid + i * 512;
        if (idx < 768) {
            int row = idx >> 2, c16 = idx & 3;
            cpa16(ws + row * 96 + c16 * 16, g_wh + row * EE + chunk * 32 + c16 * 8);
        }
    }
}

__device__ __forceinline__ int vphys(int t) {     // token -> phys pos (pair permute)
    int lp = (t & 15) >> 1;
    int pp = 2 * (lp & 3) + (lp >> 2);
    return (t & ~15) + 2 * pp + (t & 1);
}

__global__ void __launch_bounds__(512, 1) fused_kernel(const float* __restrict__ x,
                                                       float* __restrict__ out)
{
    extern __shared__ __align__(16) char sm[];
    uint32_t sb = smem_u32(sm);
    int b = blockIdx.x;
    int tid = threadIdx.x, wid = tid >> 5, lane = tid & 31;
    int g = lane >> 2, tig = lane & 3;
    long long r0 = (long long)b * TT;

    // ===================== Phase 1: QKV projection =====================
    int wm = wid >> 1, nh = wid & 1;
    int rb = wm * 32;

    float acc[12][2][4];
#pragma unroll
    for (int nt = 0; nt < 12; nt++)
#pragma unroll
        for (int mt = 0; mt < 2; mt++)
#pragma unroll
            for (int i = 0; i < 4; i++) acc[nt][mt][i] = 0.f;

    qkv_load(sb, 0, 0, x, r0);
    asm volatile("cp.async.commit_group;" ::: "memory");
    qkv_load(sb, 1, 1, x, r0);
    asm volatile("cp.async.commit_group;" ::: "memory");

    for (int c = 0; c < 12; c++) {
        if (c < 11) asm volatile("cp.async.wait_group 1;" ::: "memory");
        else        asm volatile("cp.async.wait_group 0;" ::: "memory");
        __syncthreads();

        const float* xs = (const float*)(sm + (c & 1) * QS_STAGE);
        const char*  wsb = sm + (c & 1) * QS_STAGE + XS_BYTES;
#pragma unroll
        for (int j = 0; j < 2; j++) {             // two k16 steps per 32-chunk
            uint32_t A[2][4];
#pragma unroll
            for (int mt = 0; mt < 2; mt++) {
                int r_ = rb + mt * 16 + g;
                int sw = r_ & 4;                  // XOR swizzle on float-idx bit2
                int c1 = j * 16 + 2 * tig;
                float2 lo0 = *(const float2*)&xs[r_ * 40 + (c1 ^ sw)];
                float2 lo1 = *(const float2*)&xs[(r_ + 8) * 40 + (c1 ^ sw)];
                float2 hi0 = *(const float2*)&xs[r_ * 40 + ((c1 + 8) ^ sw)];
                float2 hi1 = *(const float2*)&xs[(r_ + 8) * 40 + ((c1 + 8) ^ sw)];
                A[mt][0] = pk2h(lo0.x, lo0.y);
                A[mt][1] = pk2h(lo1.x, lo1.y);
                A[mt][2] = pk2h(hi0.x, hi0.y);
                A[mt][3] = pk2h(hi1.x, hi1.y);
            }
#pragma unroll
            for (int nt = 0; nt < 12; nt++) {
                int brow = nh * 96 + nt * 8 + g;
                uint2 bb = *(const uint2*)(wsb + brow * 96 + j * 32 + tig * 8);
                mma16h(acc[nt][0], A[0], bb.x, bb.y);
                mma16h(acc[nt][1], A[1], bb.x, bb.y);
            }
        }
        __syncthreads();

        if (c + 2 < 12) {
            qkv_load(sb, c & 1, c + 2, x, r0);
            asm volatile("cp.async.commit_group;" ::: "memory");
        }
    }

    // ============ Transition: STS accumulators -> attn layouts ============
    // (stages are dead; attn regions overlay them; data rides in acc regs)
    __syncthreads();
    const float scl = 0.125f * 1.44269504089f;
#pragma unroll
    for (int nt = 0; nt < 12; nt++) {
        int gc = nh * 96 + nt * 8;
        int mat = gc >> 6;
        int gcl = gc & 63;
#pragma unroll
        for (int mt = 0; mt < 2; mt++) {
            int row0 = rb + mt * 16 + g;
            float v0 = acc[nt][mt][0], v1 = acc[nt][mt][1];
            float v2 = acc[nt][mt][2], v3 = acc[nt][mt][3];
            if (mat == 2) {
                // V: transposed [h][tok], token pair-permuted, scalar fp16 STS
                int h0 = gcl + 2 * tig;
                int pt0 = vphys(row0), pt1 = vphys(row0 + 8);
                *(__half*)(sm + A_VS + h0 * 552 + pt0 * 2)       = __float2half_rn(v0);
                *(__half*)(sm + A_VS + (h0 + 1) * 552 + pt0 * 2) = __float2half_rn(v1);
                *(__half*)(sm + A_VS + h0 * 552 + pt1 * 2)       = __float2half_rn(v2);
                *(__half*)(sm + A_VS + (h0 + 1) * 552 + pt1 * 2) = __float2half_rn(v3);
            } else {
                if (mat == 0) { v0 *= scl; v1 *= scl; v2 *= scl; v3 *= scl; }
                // head-pair permute: phys pair = 2tig + ((gcl>>3)&1)
                int off = (gcl & ~15) + 4 * tig + 2 * ((gcl >> 3) & 1);
                int base = (mat == 0) ? A_QS : A_KS;
                *(uint32_t*)(sm + base + row0 * 144 + off * 2) = pk2h(v0, v1);
                *(uint32_t*)(sm + base + (row0 + 8) * 144 + off * 2) = pk2h(v2, v3);
            }
        }
    }
    __syncthreads();

    // ===================== Phase 2: flash attention =====================
    int w = wid;
    int m0 = w * 16;
    float o[8][4];
#pragma unroll
    for (int nt = 0; nt < 8; nt++)
#pragma unroll
        for (int e = 0; e < 4; e++) o[nt][e] = 0.f;
    float l0 = 0.f, l1 = 0.f;

    int nch = (w + 4) >> 2;
    for (int ci = 0; ci < nch; ci++) {
        int kc0 = ci * 64;
        // ---- QK^T: 4 k16 steps over head 64 ----
        float s[8][4];
#pragma unroll
        for (int nt = 0; nt < 8; nt++)
#pragma unroll
            for (int e = 0; e < 4; e++) s[nt][e] = 0.f;
#pragma unroll
        for (int j = 0; j < 4; j++) {
            uint2 qlo = *(const uint2*)(sm + A_QS + (m0 + g) * 144 + j * 32 + tig * 8);
            uint2 qhi = *(const uint2*)(sm + A_QS + (m0 + 8 + g) * 144 + j * 32 + tig * 8);
            uint32_t qa[4] = { qlo.x, qhi.x, qlo.y, qhi.y };
#pragma unroll
            for (int nt = 0; nt < 8; nt++) {
                uint2 kb2 = *(const uint2*)(sm + A_KS + (kc0 + nt * 8 + g) * 144 + j * 32 + tig * 8);
                mma16h(s[nt], qa, kb2.x, kb2.y);
            }
        }
        // ---- causal mask (C cols = keys kc0+nt*8+2tig, +1) ----
        if (kc0 + 63 > m0) {
            int r0_ = m0 + g, r1_ = m0 + 8 + g;
#pragma unroll
            for (int nt = 0; nt < 8; nt++) {
                int ka = kc0 + nt * 8 + 2 * tig, kb = ka + 1;
                s[nt][0] = (ka <= r0_) ? s[nt][0] : -INFINITY;
                s[nt][1] = (kb <= r0_) ? s[nt][1] : -INFINITY;
                s[nt][2] = (ka <= r1_) ? s[nt][2] : -INFINITY;
                s[nt][3] = (kb <= r1_) ? s[nt][3] : -INFINITY;
            }
        }
        // ---- exp (no max; exact) + l partials ----
#pragma unroll
        for (int nt = 0; nt < 8; nt++) {
            s[nt][0] = ex2f(s[nt][0]);
            s[nt][1] = ex2f(s[nt][1]);
            s[nt][2] = ex2f(s[nt][2]);
            s[nt][3] = ex2f(s[nt][3]);
            l0 += s[nt][0] + s[nt][1];
            l1 += s[nt][2] + s[nt][3];
        }
        // ---- pack P to fp16 A-frags (s dies here) ----
        uint32_t pa[4][4];
#pragma unroll
        for (int j2 = 0; j2 < 4; j2++) {
            pa[j2][0] = pk2h(s[2 * j2][0], s[2 * j2][1]);
            pa[j2][1] = pk2h(s[2 * j2][2], s[2 * j2][3]);
            pa[j2][2] = pk2h(s[2 * j2 + 1][0], s[2 * j2 + 1][1]);
            pa[j2][3] = pk2h(s[2 * j2 + 1][2], s[2 * j2 + 1][3]);
        }
        // ---- P @ V ----
#pragma unroll
        for (int j2 = 0; j2 < 4; j2++) {
#pragma unroll
            for (int nt2 = 0; nt2 < 8; nt2++) {
                uint2 vb = *(const uint2*)(sm + A_VS + (nt2 * 8 + g) * 552 +
                                           kc0 * 2 + j2 * 32 + tig * 8);
                mma16h(o[nt2], pa[j2], vb.x, vb.y);
            }
        }
    }

    // ---- final l reduction + normalize + store ----
    l0 += shflx(l0, 1); l0 += shflx(l0, 2);
    l1 += shflx(l1, 1); l1 += shflx(l1, 2);
    float inv0 = 1.0f / l0, inv1 = 1.0f / l1;
    float* ob = out + ((size_t)b * TT + m0) * HH;
#pragma unroll
    for (int nt = 0; nt < 8; nt++) {
        int cb = nt * 8 + 2 * tig;
        *(float2*)(ob + g * 64 + cb) = make_float2(o[nt][0] * inv0, o[nt][1] * inv0);
        *(float2*)(ob + (8 + g) * 64 + cb) = make_float2(o[nt][2] * inv1, o[nt][3] * inv1);
    }
}

extern "C" void kernel_launch(void* const* d_in, const int* in_sizes, int n_in,
                              void* d_out, int out_size)
{
    (void)in_sizes; (void)n_in; (void)out_size;
    const float* x  = (const float*)d_in[0];
    const float* Wq = (const float*)d_in[1];
    const float* Wk = (const float*)d_in[2];
    const float* Wv = (const float*)d_in[3];
    float* out = (float*)d_out;

    cudaFuncSetAttribute(fused_kernel, cudaFuncAttributeMaxDynamicSharedMemorySize, FUSED_SMEM);

    wt_kernel<<<(3 * HH * EE + 255) / 256, 256>>>(Wq, Wk, Wv);
    fused_kernel<<<BB, 512, FUSED_SMEM>>>(x, out);
}